// round 4
// baseline (speedup 1.0000x reference)
#include <cuda_runtime.h>
#include <cuda_bf16.h>
#include <cstdint>

// Problem constants (EncoderWithoutFlexFrontsGraphsage): N=100000, E=1600000, D=64, L=3
#define NODES_MAX 100000
#define FEATS     64

// Scratch (device globals: runtime allocation is forbidden)
__device__ __align__(16) float g_agg[NODES_MAX * FEATS];
__device__ __align__(16) float g_buf0[NODES_MAX * FEATS];
__device__ __align__(16) float g_buf1[NODES_MAX * FEATS];
__device__ __align__(16) float g_invdeg[NODES_MAX];
__device__ int g_ei64;   // 1 = edge_index is int64, 0 = int32

// ---------------------------------------------------------------------------
// Edge-index dtype detection: if data is int64 with values < 2^31, every odd
// 32-bit word is zero. OR-reduce 512 odd words; all-zero => int64.
__global__ void detect_ei_kernel(const unsigned int* __restrict__ w, int nwords) {
    __shared__ unsigned int r;
    if (threadIdx.x == 0) r = 0u;
    __syncthreads();
    int idx = 2 * threadIdx.x + 1;
    unsigned int v = (idx < nwords) ? w[idx] : 0u;
    atomicOr(&r, v);
    __syncthreads();
    if (threadIdx.x == 0) g_ei64 = (r == 0u) ? 1 : 0;
}

__device__ __forceinline__ long long load_idx(const void* ei, long long pos, int is64) {
    if (is64) return ((const long long*)ei)[pos];
    return (long long)((const int*)ei)[pos];
}

// ---------------------------------------------------------------------------
// zero a float buffer (float4 granularity; counts are multiples of 4)
__global__ void zero_kernel(float* __restrict__ p, int n4) {
    int i = blockIdx.x * blockDim.x + threadIdx.x;
    if (i < n4) ((float4*)p)[i] = make_float4(0.f, 0.f, 0.f, 0.f);
}

// ---------------------------------------------------------------------------
// in-degree accumulate
__global__ void deg_kernel(const void* __restrict__ ei,
                           float* __restrict__ deg, int E, int n) {
    int e = blockIdx.x * blockDim.x + threadIdx.x;
    if (e >= E) return;
    long long d = load_idx(ei, (long long)E + e, g_ei64);  // dst row
    if ((unsigned long long)d < (unsigned long long)n)
        atomicAdd(deg + d, 1.0f);
}

__global__ void inv_kernel(float* __restrict__ d, int n) {
    int i = blockIdx.x * blockDim.x + threadIdx.x;
    if (i < n) d[i] = 1.0f / fmaxf(d[i], 1.0f);
}

// ---------------------------------------------------------------------------
// Edge scatter: agg[dst] += x[src].  16 threads per edge, float4 per thread,
// vector reduction red.global.add.v4.f32 to minimize LSU issue count.
__global__ void scatter_kernel(const float* __restrict__ x,
                               const void* __restrict__ ei,
                               float* __restrict__ agg, int E, int n) {
    long long t = (long long)blockIdx.x * blockDim.x + threadIdx.x;
    int e = (int)(t >> 4);
    if (e >= E) return;
    int c = (int)(t & 15);
    int is64 = g_ei64;
    long long s = load_idx(ei, e, is64);
    long long d = load_idx(ei, (long long)E + e, is64);
    if ((unsigned long long)s >= (unsigned long long)n) return;
    if ((unsigned long long)d >= (unsigned long long)n) return;
    float4 v = ((const float4*)(x + (s << 6)))[c];
    float* p = agg + (d << 6) + (c << 2);
    asm volatile("red.global.add.v4.f32 [%0], {%1, %2, %3, %4};"
                 :: "l"(p), "f"(v.x), "f"(v.y), "f"(v.z), "f"(v.w)
                 : "memory");
}

// ---------------------------------------------------------------------------
// Fused layer: out[n] = relu( (agg[n]*inv_deg[n]) @ Wl^T + bl + x[n] @ Wr^T )
// One thread per node; 64 fp32 register accumulators; both 64x64 weights
// transposed into shared as [k][j] so warp-uniform LDS.128 broadcasts.
__global__ __launch_bounds__(128)
void sage_gemm_kernel(const float* __restrict__ x,
                      const float* __restrict__ agg,
                      const float* __restrict__ invdeg,
                      const float* __restrict__ Wl,
                      const float* __restrict__ bl,
                      const float* __restrict__ Wr,
                      float* __restrict__ out, int n) {
    __shared__ __align__(16) float Wls[FEATS * FEATS];  // [k][j]
    __shared__ __align__(16) float Wrs[FEATS * FEATS];  // [k][j]
    __shared__ __align__(16) float bls[FEATS];

    for (int i = threadIdx.x; i < FEATS * FEATS; i += blockDim.x) {
        int j = i >> 6, k = i & 63;
        Wls[k * FEATS + j] = Wl[i];
        Wrs[k * FEATS + j] = Wr[i];
    }
    if (threadIdx.x < FEATS) bls[threadIdx.x] = bl[threadIdx.x];
    __syncthreads();

    int node = blockIdx.x * blockDim.x + threadIdx.x;
    if (node >= n) return;

    const float4* xr = (const float4*)(x + (size_t)node * FEATS);
    const float4* ar = (const float4*)(agg + (size_t)node * FEATS);
    float inv = invdeg[node];

    float acc[FEATS];
    const float4* bv = (const float4*)bls;
#pragma unroll
    for (int j4 = 0; j4 < 16; j4++) {
        float4 b = bv[j4];
        acc[4 * j4 + 0] = b.x; acc[4 * j4 + 1] = b.y;
        acc[4 * j4 + 2] = b.z; acc[4 * j4 + 3] = b.w;
    }

    float4 xv = xr[0];
    float4 av = ar[0];
#pragma unroll 1
    for (int kq = 0; kq < 16; kq++) {
        float4 xn, an;
        if (kq < 15) { xn = xr[kq + 1]; an = ar[kq + 1]; }
        float ax[4] = {xv.x, xv.y, xv.z, xv.w};
        float aa[4] = {av.x * inv, av.y * inv, av.z * inv, av.w * inv};
#pragma unroll
        for (int kk = 0; kk < 4; kk++) {
            int k = kq * 4 + kk;
            const float4* wl4 = (const float4*)(Wls + (k << 6));
            const float4* wr4 = (const float4*)(Wrs + (k << 6));
            float a = aa[kk], xs = ax[kk];
#pragma unroll
            for (int j4 = 0; j4 < 16; j4++) {
                float4 wl = wl4[j4];
                float4 wr = wr4[j4];
                acc[4 * j4 + 0] = fmaf(a, wl.x, fmaf(xs, wr.x, acc[4 * j4 + 0]));
                acc[4 * j4 + 1] = fmaf(a, wl.y, fmaf(xs, wr.y, acc[4 * j4 + 1]));
                acc[4 * j4 + 2] = fmaf(a, wl.z, fmaf(xs, wr.z, acc[4 * j4 + 2]));
                acc[4 * j4 + 3] = fmaf(a, wl.w, fmaf(xs, wr.w, acc[4 * j4 + 3]));
            }
        }
        xv = xn; av = an;
    }

    float4* o = (float4*)(out + (size_t)node * FEATS);
#pragma unroll
    for (int j4 = 0; j4 < 16; j4++) {
        float4 v;
        v.x = fmaxf(acc[4 * j4 + 0], 0.f);
        v.y = fmaxf(acc[4 * j4 + 1], 0.f);
        v.z = fmaxf(acc[4 * j4 + 2], 0.f);
        v.w = fmaxf(acc[4 * j4 + 3], 0.f);
        o[j4] = v;
    }
}

// ---------------------------------------------------------------------------
extern "C" void kernel_launch(void* const* d_in, const int* in_sizes, int n_in,
                              void* d_out, int out_size) {
    // Identify inputs by element count (robust to metadata ordering):
    //   x : 100000*64 = 6,400,000
    //   edge_index : 2*1,600,000 = 3,200,000
    //   Wl, Wr : 3*64*64 = 12,288  (first occurrence = Wl, second = Wr)
    //   bl : 3*64 = 192
    const float* x  = nullptr;
    const void*  ei = nullptr;
    const float* Wl = nullptr;
    const float* Wr = nullptr;
    const float* bl = nullptr;
    for (int i = 0; i < n_in; i++) {
        int s = in_sizes[i];
        if (s == NODES_MAX * FEATS)      x  = (const float*)d_in[i];
        else if (s == 3200000)           ei = d_in[i];
        else if (s == 3 * FEATS * FEATS) { if (!Wl) Wl = (const float*)d_in[i]; else Wr = (const float*)d_in[i]; }
        else if (s == 3 * FEATS)         bl = (const float*)d_in[i];
    }
    if (!x || !ei || !Wl || !Wr || !bl) return;  // shape mismatch: bail safely

    int n = NODES_MAX;
    int E = 1600000;

    float *agg, *b0, *b1, *invd;
    cudaGetSymbolAddress((void**)&agg,  g_agg);
    cudaGetSymbolAddress((void**)&b0,   g_buf0);
    cudaGetSymbolAddress((void**)&b1,   g_buf1);
    cudaGetSymbolAddress((void**)&invd, g_invdeg);

    const int TB = 256;

    // Detect int64 vs int32 edge indices (device-side, graph-capturable).
    detect_ei_kernel<<<1, 256>>>((const unsigned int*)ei, 1024);

    // inverse mean-degree (constant across layers)
    {
        int n4 = (n + 3) / 4;
        zero_kernel<<<(n4 + TB - 1) / TB, TB>>>(invd, n4);
        deg_kernel<<<(E + TB - 1) / TB, TB>>>(ei, invd, E, n);
        inv_kernel<<<(n + TB - 1) / TB, TB>>>(invd, n);
    }

    const float* cur = x;
    float* outs[3] = { b0, b1, (float*)d_out };
    long long sc_threads = (long long)E * 16;
    int sc_blocks = (int)((sc_threads + TB - 1) / TB);
    int agg4 = (n * FEATS) / 4;

    for (int i = 0; i < 3; i++) {
        zero_kernel<<<(agg4 + TB - 1) / TB, TB>>>(agg, agg4);
        scatter_kernel<<<sc_blocks, TB>>>(cur, ei, agg, E, n);
        sage_gemm_kernel<<<(n + 127) / 128, 128>>>(
            cur, agg, invd, Wl + i * 4096, bl + i * 64, Wr + i * 4096,
            outs[i], n);
        cur = outs[i];
    }
}

// round 5
// speedup vs baseline: 1.0392x; 1.0392x over previous
#include <cuda_runtime.h>
#include <cuda_bf16.h>
#include <cstdint>

// Problem constants: N=100000, E=1600000, D=64, L=3
#define NODES_MAX 100000
#define EDGES_MAX 1600000
#define FEATS     64
#define SCAN_THREADS 1024

// Scratch (device globals: runtime allocation forbidden)
__device__ __align__(16) float g_agg [NODES_MAX * FEATS];
__device__ __align__(16) float g_buf0[NODES_MAX * FEATS];
__device__ __align__(16) float g_buf1[NODES_MAX * FEATS];
__device__ int g_deg     [NODES_MAX];
__device__ int g_rowstart[NODES_MAX + 1];
__device__ int g_cursor  [NODES_MAX];
__device__ int g_csr     [EDGES_MAX];
__device__ int g_ei64;   // 1 = edge_index is int64, 0 = int32

// ---------------------------------------------------------------------------
// Edge-index dtype detection: int64 values < 2^31 => every odd 32-bit word 0.
__global__ void detect_ei_kernel(const unsigned int* __restrict__ w, int nwords) {
    __shared__ unsigned int r;
    if (threadIdx.x == 0) r = 0u;
    __syncthreads();
    int idx = 2 * threadIdx.x + 1;
    unsigned int v = (idx < nwords) ? w[idx] : 0u;
    atomicOr(&r, v);
    __syncthreads();
    if (threadIdx.x == 0) g_ei64 = (r == 0u) ? 1 : 0;
}

__device__ __forceinline__ long long load_idx(const void* ei, long long pos, int is64) {
    if (is64) return ((const long long*)ei)[pos];
    return (long long)((const int*)ei)[pos];
}

// ---------------------------------------------------------------------------
__global__ void zero_int_kernel(int* __restrict__ p, int n) {
    int i = blockIdx.x * blockDim.x + threadIdx.x;
    if (i < n) p[i] = 0;
}

// in-degree histogram (int atomics, spread addresses -> near REDG floor)
__global__ void hist_kernel(const void* __restrict__ ei, int* __restrict__ deg,
                            int E, int n) {
    int e = blockIdx.x * blockDim.x + threadIdx.x;
    if (e >= E) return;
    long long d = load_idx(ei, (long long)E + e, g_ei64);
    if ((unsigned long long)d < (unsigned long long)n)
        atomicAdd(deg + d, 1);
}

// single-block two-phase exclusive scan over n+1 positions -> rowstart, cursor
__global__ void scan_kernel(const int* __restrict__ deg,
                            int* __restrict__ rowstart,
                            int* __restrict__ cursor, int n) {
    __shared__ int sums[SCAN_THREADS];
    int t = threadIdx.x;
    int C = (n + 1 + SCAN_THREADS - 1) / SCAN_THREADS;
    int beg = t * C, end = min(beg + C, n + 1);
    int s = 0;
    for (int i = beg; i < end; i++) s += (i < n) ? deg[i] : 0;
    sums[t] = s;
    __syncthreads();
    // Hillis-Steele inclusive scan
    for (int off = 1; off < SCAN_THREADS; off <<= 1) {
        int v = (t >= off) ? sums[t - off] : 0;
        __syncthreads();
        sums[t] += v;
        __syncthreads();
    }
    int running = (t == 0) ? 0 : sums[t - 1];  // exclusive offset
    for (int i = beg; i < end; i++) {
        rowstart[i] = running;
        if (i < n) { cursor[i] = running; running += deg[i]; }
    }
}

// fill CSR adjacency: csr[atomicAdd(cursor[dst])] = src
__global__ void fill_kernel(const void* __restrict__ ei,
                            int* __restrict__ cursor,
                            int* __restrict__ csr, int E, int n) {
    int e = blockIdx.x * blockDim.x + threadIdx.x;
    if (e >= E) return;
    int is64 = g_ei64;
    long long s = load_idx(ei, e, is64);
    long long d = load_idx(ei, (long long)E + e, is64);
    if ((unsigned long long)d >= (unsigned long long)n) return;
    int sc = (int)s;
    sc = max(0, min(sc, n - 1));  // clamp: no holes, no OOB
    int pos = atomicAdd(cursor + d, 1);
    csr[pos] = sc;
}

// ---------------------------------------------------------------------------
// Per-layer aggregation: warp per node, mean of neighbor rows (no atomics).
// Each lane owns 2 features (float2); each neighbor = one coalesced 256B read.
__global__ __launch_bounds__(256)
void aggregate_kernel(const float* __restrict__ x,
                      const int* __restrict__ rowstart,
                      const int* __restrict__ csr,
                      float* __restrict__ agg, int n) {
    int w = (blockIdx.x * blockDim.x + threadIdx.x) >> 5;
    if (w >= n) return;
    int lane = threadIdx.x & 31;
    int beg = rowstart[w], end = rowstart[w + 1];
    const float2* x2 = (const float2*)x;
    float ax = 0.f, ay = 0.f;
    int j = beg;
    for (; j + 4 <= end; j += 4) {
        int n0 = csr[j], n1 = csr[j + 1], n2 = csr[j + 2], n3 = csr[j + 3];
        float2 v0 = x2[(size_t)n0 * 32 + lane];
        float2 v1 = x2[(size_t)n1 * 32 + lane];
        float2 v2 = x2[(size_t)n2 * 32 + lane];
        float2 v3 = x2[(size_t)n3 * 32 + lane];
        ax += (v0.x + v1.x) + (v2.x + v3.x);
        ay += (v0.y + v1.y) + (v2.y + v3.y);
    }
    for (; j < end; j++) {
        int nb = csr[j];
        float2 v = x2[(size_t)nb * 32 + lane];
        ax += v.x; ay += v.y;
    }
    float inv = 1.0f / fmaxf((float)(end - beg), 1.0f);
    ((float2*)agg)[(size_t)w * 32 + lane] = make_float2(ax * inv, ay * inv);
}

// ---------------------------------------------------------------------------
// packed f32x2 FMA (FFMA2 — only reachable via PTX fma.rn.f32x2)
__device__ __forceinline__ unsigned long long fma2(unsigned long long a,
                                                   unsigned long long b,
                                                   unsigned long long c) {
    unsigned long long d;
    asm("fma.rn.f32x2 %0, %1, %2, %3;" : "=l"(d) : "l"(a), "l"(b), "l"(c));
    return d;
}
__device__ __forceinline__ unsigned long long bcast2(float a) {
    unsigned long long r;
    asm("mov.b64 %0, {%1, %1};" : "=l"(r) : "f"(a));
    return r;
}

// Fused layer: out = relu( agg @ Wl^T + bl + x @ Wr^T ),  agg pre-scaled by 1/deg.
// One thread per node; 32 packed f32x2 accumulators; weights transposed in
// shared as [k][j] so LDS.128 addresses are warp-uniform broadcasts.
__global__ __launch_bounds__(128)
void sage_gemm_kernel(const float* __restrict__ x,
                      const float* __restrict__ agg,
                      const float* __restrict__ Wl,
                      const float* __restrict__ bl,
                      const float* __restrict__ Wr,
                      float* __restrict__ out, int n) {
    __shared__ __align__(16) float Wls[FEATS * FEATS];  // [k][j]
    __shared__ __align__(16) float Wrs[FEATS * FEATS];  // [k][j]
    __shared__ __align__(16) float bls[FEATS];

    for (int i = threadIdx.x; i < FEATS * FEATS; i += blockDim.x) {
        int j = i >> 6, k = i & 63;
        Wls[k * FEATS + j] = Wl[i];
        Wrs[k * FEATS + j] = Wr[i];
    }
    if (threadIdx.x < FEATS) bls[threadIdx.x] = bl[threadIdx.x];
    __syncthreads();

    int node = blockIdx.x * blockDim.x + threadIdx.x;
    if (node >= n) return;

    const float4* xr = (const float4*)(x + (size_t)node * FEATS);
    const float4* ar = (const float4*)(agg + (size_t)node * FEATS);

    unsigned long long acc[32];
    const unsigned long long* b2 = (const unsigned long long*)bls;
#pragma unroll
    for (int p = 0; p < 32; p++) acc[p] = b2[p];

    float4 xv = xr[0];
    float4 av = ar[0];
#pragma unroll 1
    for (int kq = 0; kq < 16; kq++) {
        float4 xn, an;
        if (kq < 15) { xn = xr[kq + 1]; an = ar[kq + 1]; }
        float ax[4] = {xv.x, xv.y, xv.z, xv.w};
        float aa[4] = {av.x, av.y, av.z, av.w};
#pragma unroll
        for (int kk = 0; kk < 4; kk++) {
            int k = kq * 4 + kk;
            unsigned long long a2 = bcast2(aa[kk]);
            unsigned long long s2 = bcast2(ax[kk]);
            const ulonglong2* wl2 = (const ulonglong2*)(Wls + (k << 6));
            const ulonglong2* wr2 = (const ulonglong2*)(Wrs + (k << 6));
#pragma unroll
            for (int q = 0; q < 16; q++) {
                ulonglong2 wl = wl2[q];
                ulonglong2 wr = wr2[q];
                acc[2 * q]     = fma2(a2, wl.x, fma2(s2, wr.x, acc[2 * q]));
                acc[2 * q + 1] = fma2(a2, wl.y, fma2(s2, wr.y, acc[2 * q + 1]));
            }
        }
        xv = xn; av = an;
    }

    float4* o = (float4*)(out + (size_t)node * FEATS);
#pragma unroll
    for (int q = 0; q < 16; q++) {
        unsigned long long v0 = acc[2 * q], v1 = acc[2 * q + 1];
        float4 r;
        r.x = fmaxf(__uint_as_float((unsigned)v0),         0.f);
        r.y = fmaxf(__uint_as_float((unsigned)(v0 >> 32)), 0.f);
        r.z = fmaxf(__uint_as_float((unsigned)v1),         0.f);
        r.w = fmaxf(__uint_as_float((unsigned)(v1 >> 32)), 0.f);
        o[q] = r;
    }
}

// ---------------------------------------------------------------------------
extern "C" void kernel_launch(void* const* d_in, const int* in_sizes, int n_in,
                              void* d_out, int out_size) {
    // Identify inputs by element count (robust to metadata ordering):
    //   x: 6,400,000   edge_index: 3,200,000   Wl/Wr: 12,288 (1st/2nd)   bl: 192
    const float* x  = nullptr;
    const void*  ei = nullptr;
    const float* Wl = nullptr;
    const float* Wr = nullptr;
    const float* bl = nullptr;
    for (int i = 0; i < n_in; i++) {
        int s = in_sizes[i];
        if (s == NODES_MAX * FEATS)      x  = (const float*)d_in[i];
        else if (s == 2 * EDGES_MAX)     ei = d_in[i];
        else if (s == 3 * FEATS * FEATS) { if (!Wl) Wl = (const float*)d_in[i]; else Wr = (const float*)d_in[i]; }
        else if (s == 3 * FEATS)         bl = (const float*)d_in[i];
    }
    if (!x || !ei || !Wl || !Wr || !bl) return;

    int n = NODES_MAX;
    int E = EDGES_MAX;

    float *agg, *b0, *b1;
    int *deg, *rowstart, *cursor, *csr;
    cudaGetSymbolAddress((void**)&agg,      g_agg);
    cudaGetSymbolAddress((void**)&b0,       g_buf0);
    cudaGetSymbolAddress((void**)&b1,       g_buf1);
    cudaGetSymbolAddress((void**)&deg,      g_deg);
    cudaGetSymbolAddress((void**)&rowstart, g_rowstart);
    cudaGetSymbolAddress((void**)&cursor,   g_cursor);
    cudaGetSymbolAddress((void**)&csr,      g_csr);

    const int TB = 256;

    // one-time CSR build
    detect_ei_kernel<<<1, 256>>>((const unsigned int*)ei, 1024);
    zero_int_kernel<<<(n + TB - 1) / TB, TB>>>(deg, n);
    hist_kernel<<<(E + TB - 1) / TB, TB>>>(ei, deg, E, n);
    scan_kernel<<<1, SCAN_THREADS>>>(deg, rowstart, cursor, n);
    fill_kernel<<<(E + TB - 1) / TB, TB>>>(ei, cursor, csr, E, n);

    const float* cur = x;
    float* outs[3] = { b0, b1, (float*)d_out };
    int agg_blocks = (n * 32 + TB - 1) / TB;  // warp per node, 8 warps/block

    for (int i = 0; i < 3; i++) {
        aggregate_kernel<<<agg_blocks, TB>>>(cur, rowstart, csr, agg, n);
        sage_gemm_kernel<<<(n + 127) / 128, 128>>>(
            cur, agg, Wl + i * 4096, bl + i * 64, Wr + i * 4096, outs[i], n);
        cur = outs[i];
    }
}

// round 6
// speedup vs baseline: 1.3857x; 1.3335x over previous
#include <cuda_runtime.h>
#include <cuda_bf16.h>
#include <cstdint>

// Problem constants: N=100000, E=1600000, D=64, L=3
#define NODES_MAX 100000
#define EDGES_MAX 1600000
#define FEATS     64
#define SCAN_BLK  512
#define SCAN_NBLK ((NODES_MAX + 1 + SCAN_BLK - 1) / SCAN_BLK)   // 196

// Scratch (device globals: runtime allocation forbidden)
__device__ __align__(16) float g_agg [NODES_MAX * FEATS];
__device__ __align__(16) float g_buf0[NODES_MAX * FEATS];
__device__ __align__(16) float g_buf1[NODES_MAX * FEATS];
__device__ int g_deg     [NODES_MAX];
__device__ int g_rowstart[NODES_MAX + 1];
__device__ int g_cursor  [NODES_MAX];
__device__ int g_csr     [EDGES_MAX];
__device__ int g_blocksum[SCAN_NBLK];
__device__ int g_ei64;   // 1 = edge_index is int64, 0 = int32

// ---------------------------------------------------------------------------
// Edge-index dtype detection: int64 values < 2^31 => every odd 32-bit word 0.
__global__ void detect_ei_kernel(const unsigned int* __restrict__ w, int nwords) {
    __shared__ unsigned int r;
    if (threadIdx.x == 0) r = 0u;
    __syncthreads();
    int idx = 2 * threadIdx.x + 1;
    unsigned int v = (idx < nwords) ? w[idx] : 0u;
    atomicOr(&r, v);
    __syncthreads();
    if (threadIdx.x == 0) g_ei64 = (r == 0u) ? 1 : 0;
}

__device__ __forceinline__ long long load_idx(const void* ei, long long pos, int is64) {
    if (is64) return ((const long long*)ei)[pos];
    return (long long)((const int*)ei)[pos];
}

// ---------------------------------------------------------------------------
__global__ void zero_int_kernel(int* __restrict__ p, int n) {
    int i = blockIdx.x * blockDim.x + threadIdx.x;
    if (i < n) p[i] = 0;
}

// in-degree histogram
__global__ void hist_kernel(const void* __restrict__ ei, int* __restrict__ deg,
                            int E, int n) {
    int e = blockIdx.x * blockDim.x + threadIdx.x;
    if (e >= E) return;
    long long d = load_idx(ei, (long long)E + e, g_ei64);
    if ((unsigned long long)d < (unsigned long long)n)
        atomicAdd(deg + d, 1);
}

// ---------------------------------------------------------------------------
// Chip-wide exclusive scan, 3 kernels.
// 1) per-block exclusive scan of deg (element n treated as 0) -> rowstart(local), blocksum
__global__ __launch_bounds__(SCAN_BLK)
void scan_partial_kernel(const int* __restrict__ deg,
                         int* __restrict__ rowstart,
                         int* __restrict__ blocksum, int n) {
    __shared__ int sh[SCAN_BLK];
    int t = threadIdx.x;
    int i = blockIdx.x * SCAN_BLK + t;
    int v = (i < n) ? deg[i] : 0;
    sh[t] = v;
    __syncthreads();
    // Hillis-Steele inclusive scan
    for (int off = 1; off < SCAN_BLK; off <<= 1) {
        int u = (t >= off) ? sh[t - off] : 0;
        __syncthreads();
        sh[t] += u;
        __syncthreads();
    }
    if (i <= n) rowstart[i] = sh[t] - v;   // exclusive
    if (t == SCAN_BLK - 1) blocksum[blockIdx.x] = sh[t];
}

// 2) single-block exclusive scan of block sums (in place)
__global__ __launch_bounds__(256)
void scan_blocksums_kernel(int* __restrict__ blocksum, int nb) {
    __shared__ int sh[256];
    int t = threadIdx.x;
    int v = (t < nb) ? blocksum[t] : 0;
    sh[t] = v;
    __syncthreads();
    for (int off = 1; off < 256; off <<= 1) {
        int u = (t >= off) ? sh[t - off] : 0;
        __syncthreads();
        sh[t] += u;
        __syncthreads();
    }
    if (t < nb) blocksum[t] = sh[t] - v;   // exclusive
}

// 3) add block offsets; emit final rowstart + cursor
__global__ __launch_bounds__(SCAN_BLK)
void scan_addoff_kernel(int* __restrict__ rowstart,
                        const int* __restrict__ blocksum,
                        int* __restrict__ cursor, int n) {
    int i = blockIdx.x * SCAN_BLK + threadIdx.x;
    if (i > n) return;
    int r = rowstart[i] + blocksum[blockIdx.x];
    rowstart[i] = r;
    if (i < n) cursor[i] = r;
}

// fill CSR adjacency: csr[atomicAdd(cursor[dst])] = src
__global__ void fill_kernel(const void* __restrict__ ei,
                            int* __restrict__ cursor,
                            int* __restrict__ csr, int E, int n) {
    int e = blockIdx.x * blockDim.x + threadIdx.x;
    if (e >= E) return;
    int is64 = g_ei64;
    long long s = load_idx(ei, e, is64);
    long long d = load_idx(ei, (long long)E + e, is64);
    if ((unsigned long long)d >= (unsigned long long)n) return;
    int sc = (int)s;
    sc = max(0, min(sc, n - 1));  // clamp: no holes, no OOB
    int pos = atomicAdd(cursor + d, 1);
    csr[pos] = sc;
}

// ---------------------------------------------------------------------------
// Per-layer aggregation: warp per node, mean of neighbor rows (no atomics).
// Each lane owns 2 features (float2); each neighbor = one coalesced 256B read.
__global__ __launch_bounds__(256)
void aggregate_kernel(const float* __restrict__ x,
                      const int* __restrict__ rowstart,
                      const int* __restrict__ csr,
                      float* __restrict__ agg, int n) {
    int w = (blockIdx.x * blockDim.x + threadIdx.x) >> 5;
    if (w >= n) return;
    int lane = threadIdx.x & 31;
    int beg = rowstart[w], end = rowstart[w + 1];
    const float2* x2 = (const float2*)x;
    float ax = 0.f, ay = 0.f;
    int j = beg;
    for (; j + 4 <= end; j += 4) {
        int n0 = csr[j], n1 = csr[j + 1], n2 = csr[j + 2], n3 = csr[j + 3];
        float2 v0 = x2[(size_t)n0 * 32 + lane];
        float2 v1 = x2[(size_t)n1 * 32 + lane];
        float2 v2 = x2[(size_t)n2 * 32 + lane];
        float2 v3 = x2[(size_t)n3 * 32 + lane];
        ax += (v0.x + v1.x) + (v2.x + v3.x);
        ay += (v0.y + v1.y) + (v2.y + v3.y);
    }
    for (; j < end; j++) {
        int nb = csr[j];
        float2 v = x2[(size_t)nb * 32 + lane];
        ax += v.x; ay += v.y;
    }
    float inv = 1.0f / fmaxf((float)(end - beg), 1.0f);
    ((float2*)agg)[(size_t)w * 32 + lane] = make_float2(ax * inv, ay * inv);
}

// ---------------------------------------------------------------------------
// packed f32x2 FMA (FFMA2 — only reachable via PTX fma.rn.f32x2)
__device__ __forceinline__ unsigned long long fma2(unsigned long long a,
                                                   unsigned long long b,
                                                   unsigned long long c) {
    unsigned long long d;
    asm("fma.rn.f32x2 %0, %1, %2, %3;" : "=l"(d) : "l"(a), "l"(b), "l"(c));
    return d;
}
__device__ __forceinline__ unsigned long long bcast2(float a) {
    unsigned long long r;
    asm("mov.b64 %0, {%1, %1};" : "=l"(r) : "f"(a));
    return r;
}

// Fused layer: out = relu( agg @ Wl^T + bl + x @ Wr^T ),  agg pre-scaled by 1/deg.
// One thread per node; 32 packed f32x2 accumulators; weights transposed in
// shared as [k][j] so LDS.128 addresses are warp-uniform broadcasts.
__global__ __launch_bounds__(128)
void sage_gemm_kernel(const float* __restrict__ x,
                      const float* __restrict__ agg,
                      const float* __restrict__ Wl,
                      const float* __restrict__ bl,
                      const float* __restrict__ Wr,
                      float* __restrict__ out, int n) {
    __shared__ __align__(16) float Wls[FEATS * FEATS];  // [k][j]
    __shared__ __align__(16) float Wrs[FEATS * FEATS];  // [k][j]
    __shared__ __align__(16) float bls[FEATS];

    for (int i = threadIdx.x; i < FEATS * FEATS; i += blockDim.x) {
        int j = i >> 6, k = i & 63;
        Wls[k * FEATS + j] = Wl[i];
        Wrs[k * FEATS + j] = Wr[i];
    }
    if (threadIdx.x < FEATS) bls[threadIdx.x] = bl[threadIdx.x];
    __syncthreads();

    int node = blockIdx.x * blockDim.x + threadIdx.x;
    if (node >= n) return;

    const float4* xr = (const float4*)(x + (size_t)node * FEATS);
    const float4* ar = (const float4*)(agg + (size_t)node * FEATS);

    unsigned long long acc[32];
    const unsigned long long* b2 = (const unsigned long long*)bls;
#pragma unroll
    for (int p = 0; p < 32; p++) acc[p] = b2[p];

    float4 xv = xr[0];
    float4 av = ar[0];
#pragma unroll 1
    for (int kq = 0; kq < 16; kq++) {
        float4 xn, an;
        if (kq < 15) { xn = xr[kq + 1]; an = ar[kq + 1]; }
        float ax[4] = {xv.x, xv.y, xv.z, xv.w};
        float aa[4] = {av.x, av.y, av.z, av.w};
#pragma unroll
        for (int kk = 0; kk < 4; kk++) {
            int k = kq * 4 + kk;
            unsigned long long a2 = bcast2(aa[kk]);
            unsigned long long s2 = bcast2(ax[kk]);
            const ulonglong2* wl2 = (const ulonglong2*)(Wls + (k << 6));
            const ulonglong2* wr2 = (const ulonglong2*)(Wrs + (k << 6));
#pragma unroll
            for (int q = 0; q < 16; q++) {
                ulonglong2 wl = wl2[q];
                ulonglong2 wr = wr2[q];
                acc[2 * q]     = fma2(a2, wl.x, fma2(s2, wr.x, acc[2 * q]));
                acc[2 * q + 1] = fma2(a2, wl.y, fma2(s2, wr.y, acc[2 * q + 1]));
            }
        }
        xv = xn; av = an;
    }

    float4* o = (float4*)(out + (size_t)node * FEATS);
#pragma unroll
    for (int q = 0; q < 16; q++) {
        unsigned long long v0 = acc[2 * q], v1 = acc[2 * q + 1];
        float4 r;
        r.x = fmaxf(__uint_as_float((unsigned)v0),         0.f);
        r.y = fmaxf(__uint_as_float((unsigned)(v0 >> 32)), 0.f);
        r.z = fmaxf(__uint_as_float((unsigned)v1),         0.f);
        r.w = fmaxf(__uint_as_float((unsigned)(v1 >> 32)), 0.f);
        o[q] = r;
    }
}

// ---------------------------------------------------------------------------
extern "C" void kernel_launch(void* const* d_in, const int* in_sizes, int n_in,
                              void* d_out, int out_size) {
    // Identify inputs by element count (robust to metadata ordering):
    //   x: 6,400,000   edge_index: 3,200,000   Wl/Wr: 12,288 (1st/2nd)   bl: 192
    const float* x  = nullptr;
    const void*  ei = nullptr;
    const float* Wl = nullptr;
    const float* Wr = nullptr;
    const float* bl = nullptr;
    for (int i = 0; i < n_in; i++) {
        int s = in_sizes[i];
        if (s == NODES_MAX * FEATS)      x  = (const float*)d_in[i];
        else if (s == 2 * EDGES_MAX)     ei = d_in[i];
        else if (s == 3 * FEATS * FEATS) { if (!Wl) Wl = (const float*)d_in[i]; else Wr = (const float*)d_in[i]; }
        else if (s == 3 * FEATS)         bl = (const float*)d_in[i];
    }
    if (!x || !ei || !Wl || !Wr || !bl) return;

    int n = NODES_MAX;
    int E = EDGES_MAX;

    float *agg, *b0, *b1;
    int *deg, *rowstart, *cursor, *csr, *bsum;
    cudaGetSymbolAddress((void**)&agg,      g_agg);
    cudaGetSymbolAddress((void**)&b0,       g_buf0);
    cudaGetSymbolAddress((void**)&b1,       g_buf1);
    cudaGetSymbolAddress((void**)&deg,      g_deg);
    cudaGetSymbolAddress((void**)&rowstart, g_rowstart);
    cudaGetSymbolAddress((void**)&cursor,   g_cursor);
    cudaGetSymbolAddress((void**)&csr,      g_csr);
    cudaGetSymbolAddress((void**)&bsum,     g_blocksum);

    const int TB = 256;

    // one-time (per replay) CSR build
    detect_ei_kernel<<<1, 256>>>((const unsigned int*)ei, 1024);
    zero_int_kernel<<<(n + TB - 1) / TB, TB>>>(deg, n);
    hist_kernel<<<(E + TB - 1) / TB, TB>>>(ei, deg, E, n);
    scan_partial_kernel<<<SCAN_NBLK, SCAN_BLK>>>(deg, rowstart, bsum, n);
    scan_blocksums_kernel<<<1, 256>>>(bsum, SCAN_NBLK);
    scan_addoff_kernel<<<SCAN_NBLK, SCAN_BLK>>>(rowstart, bsum, cursor, n);
    fill_kernel<<<(E + TB - 1) / TB, TB>>>(ei, cursor, csr, E, n);

    const float* cur = x;
    float* outs[3] = { b0, b1, (float*)d_out };
    int agg_blocks = (n * 32 + TB - 1) / TB;  // warp per node, 8 warps/block

    for (int i = 0; i < 3; i++) {
        aggregate_kernel<<<agg_blocks, TB>>>(cur, rowstart, csr, agg, n);
        sage_gemm_kernel<<<(n + 127) / 128, 128>>>(
            cur, agg, Wl + i * 4096, bl + i * 64, Wr + i * 4096, outs[i], n);
        cur = outs[i];
    }
}